// round 1
// baseline (speedup 1.0000x reference)
#include <cuda_runtime.h>
#include <math.h>
#include <stdint.h>

#define EPSF 1e-6f
#define NBATCH 4096
#define RS 130            // padded row stride (transposed layout [K][RS])

// ---------------------------------------------------------------------------
// packed fp32x2 FMA (Blackwell): d = a*b + c elementwise on 2 packed floats
// ---------------------------------------------------------------------------
__device__ __forceinline__ float2 ffma2(float2 a, float2 b, float2 c) {
    float2 d;
    asm("fma.rn.f32x2 %0, %1, %2, %3;"
        : "=l"(reinterpret_cast<unsigned long long&>(d))
        : "l"(reinterpret_cast<unsigned long long&>(a)),
          "l"(reinterpret_cast<unsigned long long&>(b)),
          "l"(reinterpret_cast<unsigned long long&>(c)));
    return d;
}

// Accurate sinf (Cody-Waite, relative-accurate near zeros). |x| <= ~40.
__device__ __forceinline__ float my_sinf(float x) {
    float k = rintf(x * 0.318309886183790672f);
    float r = fmaf(k, -3.14159274101257324f, x);     // x - k*pi_hi (exact product FMA)
    r = fmaf(k, 8.742278012618954e-8f, r);           // - k*pi_lo (pi_lo < 0)
    float r2 = r * r;
    float p = -2.50521083854e-08f;
    p = fmaf(p, r2, 2.75573192239e-06f);
    p = fmaf(p, r2, -1.98412698413e-04f);
    p = fmaf(p, r2, 8.33333333333e-03f);
    p = fmaf(p, r2, -1.66666666667e-01f);
    float s = fmaf(p * r2, r, r);
    int ki = __float2int_rn(k);
    return (ki & 1) ? -s : s;
}

__device__ __forceinline__ float leaky_f(float x) { return x >= 0.f ? x : 0.1f * x; }

// ---------------------------------------------------------------------------
// Er head: one thread per batch row
// ---------------------------------------------------------------------------
__global__ void er_kernel(const float* __restrict__ ego_y,
                          const float* __restrict__ W_sel, const float* __restrict__ b_sel,
                          const float* __restrict__ W_s0,  const float* __restrict__ b_s0,
                          const float* __restrict__ W_map, const float* __restrict__ b_map,
                          const float* __restrict__ W_efc, const float* __restrict__ b_efc,
                          float* __restrict__ out)
{
    __shared__ float sWm[384], sbm[8], sWs[16], sbs[4], sW0[32], sb0[8], sWe[16], sbe[2];
    int t = threadIdx.x;
    for (int i = t; i < 384; i += blockDim.x) sWm[i] = W_map[i];
    if (t < 16) sWs[t] = W_sel[t];
    if (t < 4)  sbs[t] = b_sel[t];
    if (t < 32) sW0[t] = W_s0[t];
    if (t < 8)  { sb0[t] = b_s0[t]; sbm[t] = b_map[t]; }
    if (t < 16) sWe[t] = W_efc[t];
    if (t < 2)  sbe[t] = b_efc[t];
    __syncthreads();

    int b = blockIdx.x * blockDim.x + t;
    if (b >= NBATCH) return;
    float ey = ego_y[b];
    const float lane0 = 13.55f, lane1 = 17.45f, lane2 = 21.12f, lane3 = 24.91f;
    float dy[4] = { lane0 - ey, lane1 - ey, lane2 - ey, lane3 - ey };

    float z[4];
    #pragma unroll
    for (int o = 0; o < 4; o++) {
        float a = sbs[o];
        #pragma unroll
        for (int i = 0; i < 4; i++) a = fmaf(dy[i], sWs[o*4+i], a);
        z[o] = a;
    }
    float m = fmaxf(fmaxf(z[0], z[1]), fmaxf(z[2], z[3]));
    float e[4], ssum = 0.f;
    #pragma unroll
    for (int i = 0; i < 4; i++) { e[i] = expf(z[i] - m); ssum += e[i]; }
    float x[4];
    #pragma unroll
    for (int i = 0; i < 4; i++) x[i] = (e[i] / ssum) * dy[i];

    float f[48];
    #pragma unroll
    for (int i = 0; i < 4; i++) f[i] = x[i];
    #pragma unroll
    for (int j = 0; j < 8; j++) {
        float arg = sb0[j];
        #pragma unroll
        for (int i = 0; i < 4; i++) arg = fmaf(x[i], sW0[j*4+i], arg);
        float s = my_sinf(arg) + EPSF;
        f[4 + j] = s;
        f[28 + j] = 1.0f / s;
    }
    #pragma unroll
    for (int i = 0; i < 4; i++) {
        float sq = x[i]*x[i] + EPSF;
        float cb = x[i]*x[i]*x[i] + EPSF;
        float ex = expf(x[i]) + EPSF;
        f[12+i] = sq;           f[36+i] = 1.0f / sq;
        f[16+i] = cb;           f[40+i] = 1.0f / cb;
        f[20+i] = ex;           f[44+i] = 1.0f / ex;
        f[24+i] = 1.0f / (x[i] + EPSF);
    }

    float y[8];
    #pragma unroll
    for (int o = 0; o < 8; o++) {
        float a = sbm[o];
        #pragma unroll
        for (int k = 0; k < 48; k++) a = fmaf(f[k], sWm[o*48+k], a);
        y[o] = leaky_f(a);
    }
    float r0 = sbe[0], r1 = sbe[1];
    #pragma unroll
    for (int k = 0; k < 8; k++) {
        r0 = fmaf(y[k], sWe[k],     r0);
        r1 = fmaf(y[k], sWe[8 + k], r1);
    }
    out[b*4 + 0] = r0;
    out[b*4 + 1] = r1;
}

// ---------------------------------------------------------------------------
// En net
// ---------------------------------------------------------------------------

// write one _auge block (50 features) into transposed smem column
__device__ __forceinline__ void write_aug(float* __restrict__ Acol, int base,
                                          float dx, float dy,
                                          const float* __restrict__ W_s1,
                                          const float* __restrict__ b_s1)
{
    Acol[(base+0)*RS] = dx;
    Acol[(base+1)*RS] = dy;
    #pragma unroll 1
    for (int j = 0; j < 17; j++) {
        float arg = fmaf(dx, __ldg(W_s1 + 2*j),
                    fmaf(dy, __ldg(W_s1 + 2*j + 1), __ldg(b_s1 + j)));
        float s = my_sinf(arg) + EPSF;
        Acol[(base+2+j)*RS]  = s;
        Acol[(base+27+j)*RS] = 1.0f / s;
    }
    float sqx = dx*dx + EPSF, sqy = dy*dy + EPSF;
    float cbx = dx*dx*dx + EPSF, cby = dy*dy*dy + EPSF;
    float exx = expf(dx) + EPSF, exy = expf(dy) + EPSF;
    Acol[(base+19)*RS] = sqx;  Acol[(base+20)*RS] = sqy;
    Acol[(base+21)*RS] = cbx;  Acol[(base+22)*RS] = cby;
    Acol[(base+23)*RS] = exx;  Acol[(base+24)*RS] = exy;
    Acol[(base+25)*RS] = 1.0f / (dx + EPSF);
    Acol[(base+26)*RS] = 1.0f / (dy + EPSF);
    Acol[(base+44)*RS] = 1.0f / sqx;  Acol[(base+45)*RS] = 1.0f / sqy;
    Acol[(base+46)*RS] = 1.0f / cbx;  Acol[(base+47)*RS] = 1.0f / cby;
    Acol[(base+48)*RS] = 1.0f / exx;  Acol[(base+49)*RS] = 1.0f / exy;
}

// C_T[o][r] = act(b[o] + sum_k A_T[k][r] * W[o][k]) over 128 rows.
// rt in [0,16): owns row-pairs p = rt+16j (j<4).  ot: owns outs ot*TO..+TO-1.
template<int K, int TO, int LDW>
__device__ __forceinline__ void gemm_tile(const float* __restrict__ At,
                                          const float* __restrict__ Wg,
                                          const float* __restrict__ bg,
                                          float* __restrict__ Ct,
                                          int rt, int ot)
{
    float2 acc[4][TO];
    #pragma unroll
    for (int i = 0; i < TO; i++) {
        float bo = __ldg(bg + ot*TO + i);
        #pragma unroll
        for (int j = 0; j < 4; j++) acc[j][i] = make_float2(bo, bo);
    }
    const float* xbase = At + 2*rt;
    for (int k = 0; k < K; k += 2) {
        float2 x0[4], x1[4];
        #pragma unroll
        for (int j = 0; j < 4; j++) {
            x0[j] = *reinterpret_cast<const float2*>(xbase + k*RS       + 32*j);
            x1[j] = *reinterpret_cast<const float2*>(xbase + (k+1)*RS   + 32*j);
        }
        #pragma unroll
        for (int i = 0; i < TO; i++) {
            float2 w = __ldg(reinterpret_cast<const float2*>(Wg + (ot*TO + i)*LDW + k));
            float2 wa = make_float2(w.x, w.x);
            float2 wb = make_float2(w.y, w.y);
            #pragma unroll
            for (int j = 0; j < 4; j++) {
                acc[j][i] = ffma2(x0[j], wa, acc[j][i]);
                acc[j][i] = ffma2(x1[j], wb, acc[j][i]);
            }
        }
    }
    #pragma unroll
    for (int i = 0; i < TO; i++) {
        #pragma unroll
        for (int j = 0; j < 4; j++) {
            float2 v = acc[j][i];
            v.x = leaky_f(v.x);
            v.y = leaky_f(v.y);
            *reinterpret_cast<float2*>(Ct + (ot*TO + i)*RS + 2*rt + 32*j) = v;
        }
    }
}

// smem layout (floats): region0 [128][RS] (features A_T[114][RS], then h2_T),
// region1 h1_T[256][RS], then en[128][2], logits[128]
#define SM_R0   (128*RS)
#define SM_R1   (256*RS)
#define SM_EN   (SM_R0 + SM_R1)
#define SM_LG   (SM_EN + 256)
#define SM_TOT  (SM_LG + 128)

__global__ void __launch_bounds__(512, 1)
en_kernel(const float* __restrict__ Pn,  const float* __restrict__ Pego,
          const float* __restrict__ Vn,  const float* __restrict__ Vego,
          const float* __restrict__ Cn,
          const float* __restrict__ W_s1, const float* __restrict__ b_s1,
          const float* __restrict__ W1,  const float* __restrict__ b1,
          const float* __restrict__ W2,  const float* __restrict__ b2,
          const float* __restrict__ W3,  const float* __restrict__ b3,
          const float* __restrict__ Ww,  const float* __restrict__ bw,
          float* __restrict__ out)
{
    extern __shared__ float sm[];
    float* At  = sm;              // features (transposed), later h2_T
    float* h1T = sm + SM_R0;
    float* enb = sm + SM_EN;
    float* lgb = sm + SM_LG;

    int tid = threadIdx.x;
    int blk = blockIdx.x;

    // ---- phase 0: features, 2 threads per row (P-part / V-part) ----
    if (tid < 256) {
        int r = tid >> 1;
        int part = tid & 1;
        int b = blk*2 + (r >> 6);
        int n = r & 63;
        int idx2 = (b*64 + n) * 2;
        float* Acol = At + r;
        if (part == 0) {
            float pex = Pego[b*2], pey = Pego[b*2+1];
            float pnx = Pn[idx2],  pny = Pn[idx2+1];
            float dx = pnx - pex,  dy = pny - pey;
            Acol[0*RS] = pex;  Acol[1*RS] = pey;
            Acol[2*RS] = pnx;  Acol[3*RS] = pny;
            Acol[4*RS] = dx;   Acol[5*RS] = dy;
            write_aug(Acol, 6, dx, dy, W_s1, b_s1);
            Acol[112*RS] = Cn[idx2];
            Acol[113*RS] = Cn[idx2+1];
        } else {
            float vex = Vego[b*2], vey = Vego[b*2+1];
            float vnx = Vn[idx2],  vny = Vn[idx2+1];
            float dx = vnx - vex,  dy = vny - vey;
            Acol[56*RS] = vex;  Acol[57*RS] = vey;
            Acol[58*RS] = vnx;  Acol[59*RS] = vny;
            Acol[60*RS] = dx;   Acol[61*RS] = dy;
            write_aug(Acol, 62, dx, dy, W_s1, b_s1);
        }
    }
    __syncthreads();

    int rt = tid & 15;
    int ot = tid >> 4;

    // ---- layer1: [128,114] -> [128,256], leaky ----
    gemm_tile<114, 8, 114>(At, W1, b1, h1T, rt, ot);
    __syncthreads();

    // ---- layer2: [128,256] -> [128,128], leaky (writes into At region) ----
    gemm_tile<256, 4, 256>(h1T, W2, b2, At, rt, ot);
    __syncthreads();

    // ---- layer3 + logits ----
    if (tid < 128) {
        int r = tid;
        float a0 = __ldg(b3), a1 = __ldg(b3 + 1);
        #pragma unroll 4
        for (int k = 0; k < 128; k++) {
            float h = At[k*RS + r];
            a0 = fmaf(h, __ldg(W3 + k),       a0);
            a1 = fmaf(h, __ldg(W3 + 128 + k), a1);
        }
        enb[r*2]   = a0;
        enb[r*2+1] = a1;
        int b = blk*2 + (r >> 6);
        int n = r & 63;
        int idx2 = (b*64 + n) * 2;
        float pnx = Pn[idx2], pny = Pn[idx2+1];
        float dx = pnx - Pego[b*2], dy = pny - Pego[b*2+1];
        float lg = __ldg(bw);
        lg = fmaf(__ldg(Ww+0), a0,  lg);
        lg = fmaf(__ldg(Ww+1), a1,  lg);
        lg = fmaf(__ldg(Ww+2), pnx, lg);
        lg = fmaf(__ldg(Ww+3), pny, lg);
        lg = fmaf(__ldg(Ww+4), dx,  lg);
        lg = fmaf(__ldg(Ww+5), dy,  lg);
        lgb[r] = lg;
    }
    __syncthreads();

    // ---- softmax over 64 neighbors + weighted sum (warp 0 -> batch0, warp 1 -> batch1)
    if (tid < 64) {
        int w = tid >> 5, l = tid & 31;
        int base = w * 64;
        float v0 = lgb[base + l], v1 = lgb[base + 32 + l];
        float m = fmaxf(v0, v1);
        #pragma unroll
        for (int off = 16; off; off >>= 1)
            m = fmaxf(m, __shfl_xor_sync(0xffffffffu, m, off));
        float e0 = expf(v0 - m), e1 = expf(v1 - m);
        float s  = e0 + e1;
        float n0 = e0 * enb[(base+l)*2]     + e1 * enb[(base+32+l)*2];
        float n1 = e0 * enb[(base+l)*2 + 1] + e1 * enb[(base+32+l)*2 + 1];
        #pragma unroll
        for (int off = 16; off; off >>= 1) {
            s  += __shfl_xor_sync(0xffffffffu, s,  off);
            n0 += __shfl_xor_sync(0xffffffffu, n0, off);
            n1 += __shfl_xor_sync(0xffffffffu, n1, off);
        }
        if (l == 0) {
            int b = blk*2 + w;
            out[b*4 + 2] = n0 / s;
            out[b*4 + 3] = n1 / s;
        }
    }
}

// ---------------------------------------------------------------------------
extern "C" void kernel_launch(void* const* d_in, const int* in_sizes, int n_in,
                              void* d_out, int out_size)
{
    const float* ego_y = (const float*)d_in[0];
    const float* Pn    = (const float*)d_in[1];
    const float* Pego  = (const float*)d_in[2];
    const float* Vn    = (const float*)d_in[3];
    const float* Vego  = (const float*)d_in[4];
    const float* Cn    = (const float*)d_in[5];
    const float* W_sel = (const float*)d_in[6];
    const float* b_sel = (const float*)d_in[7];
    const float* W_s0  = (const float*)d_in[8];
    const float* b_s0  = (const float*)d_in[9];
    const float* W_map = (const float*)d_in[10];
    const float* b_map = (const float*)d_in[11];
    const float* W_efc = (const float*)d_in[12];
    const float* b_efc = (const float*)d_in[13];
    const float* W_s1  = (const float*)d_in[14];
    const float* b_s1  = (const float*)d_in[15];
    const float* W1    = (const float*)d_in[16];
    const float* b1    = (const float*)d_in[17];
    const float* W2    = (const float*)d_in[18];
    const float* b2    = (const float*)d_in[19];
    const float* W3    = (const float*)d_in[20];
    const float* b3    = (const float*)d_in[21];
    const float* Ww    = (const float*)d_in[22];
    const float* bw    = (const float*)d_in[23];
    float* out = (float*)d_out;

    size_t smem_bytes = (size_t)SM_TOT * sizeof(float);
    cudaFuncSetAttribute(en_kernel, cudaFuncAttributeMaxDynamicSharedMemorySize,
                         (int)smem_bytes);

    er_kernel<<<16, 256>>>(ego_y, W_sel, b_sel, W_s0, b_s0, W_map, b_map,
                           W_efc, b_efc, out);
    en_kernel<<<NBATCH/2, 512, smem_bytes>>>(Pn, Pego, Vn, Vego, Cn,
                                             W_s1, b_s1, W1, b1, W2, b2,
                                             W3, b3, Ww, bw, out);
}